// round 14
// baseline (speedup 1.0000x reference)
#include <cuda_runtime.h>
#include <cuda_bf16.h>
#include <cstdint>
#include <cstddef>

#define SEQ   256
#define BATCH 32
#define NVOC  10000
#define NVPAD 10112     // 79 * 128
#define NH    256
#define NG    1024      // NH * 4 gates
#define MTOT  8192      // SEQ * BATCH
#define NRC   128       // recurrence CTAs
#define NDT   (79 * 64) // decoder tiles

// ---------------- scratch (static device globals; no allocation) ----------------
__device__ float    g_gx[(size_t)MTOT * NG];     // layer-0 gate inputs (32 MB)
__device__ unsigned g_cnt;                       // barrier arrival counter
__device__ unsigned g_flag;                      // release flag (reaches SEQ+1)

// h exchange planes (bf16 hi/lo split, ping-pong parity)
__device__ __nv_bfloat16 g_h1hi[2][BATCH * NH];
__device__ __nv_bfloat16 g_h1lo[2][BATCH * NH];
__device__ __nv_bfloat16 g_h2hi[2][BATCH * NH];
__device__ __nv_bfloat16 g_h2lo[2][BATCH * NH];

// bf16 split buffers for tensor-core decoder
__device__ __nv_bfloat16 g_Ahi[(size_t)MTOT * NH];
__device__ __nv_bfloat16 g_Alo[(size_t)MTOT * NH];
__device__ __nv_bfloat16 g_Whi[(size_t)NVPAD * NH];
__device__ __nv_bfloat16 g_Wlo[(size_t)NVPAD * NH];

// ---------------- init: zero h planes + barrier ----------------
__global__ void init_state() {
    int t = blockIdx.x * blockDim.x + threadIdx.x;
    int nthr = gridDim.x * blockDim.x;
    uint32_t* p1h = (uint32_t*)g_h1hi; uint32_t* p1l = (uint32_t*)g_h1lo;
    uint32_t* p2h = (uint32_t*)g_h2hi; uint32_t* p2l = (uint32_t*)g_h2lo;
    for (int i = t; i < 2 * BATCH * NH / 2; i += nthr) {
        p1h[i] = 0u; p1l[i] = 0u; p2h[i] = 0u; p2l[i] = 0u;
    }
    if (t == 0) { g_cnt = 0u; g_flag = 0u; }
}

// ---------------- gx GEMM (layer 0 only, fp32 — proven) ----------------
__global__ __launch_bounds__(256) void gemm_gx(
    const float* __restrict__ embed_W,
    const int*   __restrict__ tokens,
    const float* __restrict__ Wx,      // [256][1024]
    const float* __restrict__ bias)    // [1024]
{
    __shared__ float As[16][132];
    __shared__ float Bs[16][132];

    const int m0 = blockIdx.y * 128;
    const int n0 = blockIdx.x * 128;
    const int t  = threadIdx.x;
    const int tx = t & 15;
    const int ty = t >> 4;

    const int r0 = t >> 2;
    const int r1 = r0 + 64;
    const int kq = (t & 3) * 4;
    const float* ap0 = embed_W + (size_t)tokens[m0 + r0] * NH;
    const float* ap1 = embed_W + (size_t)tokens[m0 + r1] * NH;

    float acc[8][8];
    #pragma unroll
    for (int i = 0; i < 8; i++)
        #pragma unroll
        for (int j = 0; j < 8; j++) acc[i][j] = 0.f;

    for (int k0 = 0; k0 < NH; k0 += 16) {
        {
            float4 v0 = *(const float4*)(ap0 + k0 + kq);
            float4 v1 = *(const float4*)(ap1 + k0 + kq);
            As[kq + 0][r0] = v0.x; As[kq + 1][r0] = v0.y;
            As[kq + 2][r0] = v0.z; As[kq + 3][r0] = v0.w;
            As[kq + 0][r1] = v1.x; As[kq + 1][r1] = v1.y;
            As[kq + 2][r1] = v1.z; As[kq + 3][r1] = v1.w;
        }
        #pragma unroll
        for (int i = 0; i < 2; i++) {
            int lin = t + i * 256;
            int kk  = lin >> 5;
            int nq  = (lin & 31) * 4;
            *(float4*)&Bs[kk][nq] = *(const float4*)(Wx + (size_t)(k0 + kk) * NG + n0 + nq);
        }
        __syncthreads();
        #pragma unroll
        for (int kk = 0; kk < 16; kk++) {
            float a[8], b[8];
            *(float4*)&a[0] = *(const float4*)&As[kk][ty * 8];
            *(float4*)&a[4] = *(const float4*)&As[kk][ty * 8 + 4];
            *(float4*)&b[0] = *(const float4*)&Bs[kk][tx * 8];
            *(float4*)&b[4] = *(const float4*)&Bs[kk][tx * 8 + 4];
            #pragma unroll
            for (int i = 0; i < 8; i++)
                #pragma unroll
                for (int j = 0; j < 8; j++)
                    acc[i][j] += a[i] * b[j];
        }
        __syncthreads();
    }

    #pragma unroll
    for (int i = 0; i < 8; i++) {
        size_t m = (size_t)(m0 + ty * 8 + i);
        float* op = g_gx + m * NG + n0 + tx * 8;
        const float* bp = bias + n0 + tx * 8;
        #pragma unroll
        for (int j = 0; j < 8; j++) op[j] = acc[i][j] + bp[j];
    }
}

// ---------------- MMA / async-copy macros ----------------
#define LDM_A(r0,r1,r2,r3,addr) \
    asm volatile("ldmatrix.sync.aligned.m8n8.x4.shared.b16 {%0,%1,%2,%3}, [%4];" \
        : "=r"(r0), "=r"(r1), "=r"(r2), "=r"(r3) : "r"(addr))

#define MMA_BF16(c, a, b) \
    asm volatile("mma.sync.aligned.m16n8k16.row.col.f32.bf16.bf16.f32 " \
        "{%0,%1,%2,%3}, {%4,%5,%6,%7}, {%8,%9}, {%0,%1,%2,%3};" \
        : "+f"((c)[0]), "+f"((c)[1]), "+f"((c)[2]), "+f"((c)[3]) \
        : "r"((a)[0]), "r"((a)[1]), "r"((a)[2]), "r"((a)[3]), "r"((b)[0]), "r"((b)[1]))

#define CP_ASYNC16(dst, src) \
    asm volatile("cp.async.ca.shared.global [%0],[%1],16;" :: "r"(dst), "l"(src))
#define CP_COMMIT() asm volatile("cp.async.commit_group;" ::: "memory")
#define CP_WAIT1()  asm volatile("cp.async.wait_group 1;" ::: "memory")
#define CP_WAIT0()  asm volatile("cp.async.wait_group 0;" ::: "memory")

// ---------------- smem layout (shared by both paths of fused_all) ----------------
// Recurrence: B planes (hi/lo) + 4 A planes; fp32 partials ALIAS the A planes
// (A planes are dead after the MMA loop; extra __syncthreads guards the overwrite).
#define RPITCH 264
#define PLANE_B (32 * RPITCH * 2)               // 16896 B per plane
#define OFF_BHI 0
#define OFF_BLO PLANE_B
#define OFF_A   (2 * PLANE_B)                   // 4 A planes
#define RS_BYTES (OFF_A + 4 * PLANE_B)          // 101,376 B
// Decoder: 2 stages x 4 tiles x 10240 B = 81,920 B <= RS_BYTES
#define DTILE   10240
#define DSTAGE  (4 * DTILE)

// ---------------- recurrence path (round-10/13 kernel + partial aliasing) ----------------
__device__ __forceinline__ void recurrence_path(
    char* smc,
    const float* __restrict__ Wh0, const float* __restrict__ Wx1,
    const float* __restrict__ Wh1, const float* __restrict__ b1,
    float* __restrict__ h1_out, float* __restrict__ h2_out)
{
    __nv_bfloat16* sBhi = (__nv_bfloat16*)(smc + OFF_BHI);
    __nv_bfloat16* sBlo = (__nv_bfloat16*)(smc + OFF_BLO);
    float*         sPart = (float*)(smc + OFF_A);      // aliases A planes

    const int t    = threadIdx.x;
    const int warp = t >> 5;
    const int lane = t & 31;
    const int kg0  = blockIdx.x * 8;
    const int c    = t & 7;
    const int b    = t >> 3;
    const int k    = (kg0 + c) >> 2;
    const bool owner = (t & 3) == 0;
    const unsigned base = lane & ~3u;

    for (int idx = t; idx < 3 * 8 * NH; idx += 256) {
        int m   = idx >> 11;
        int rem = idx & 2047;
        int j   = rem >> 8;
        int kk  = rem & 255;
        const float* src = (m == 0) ? Wh0 : ((m == 1) ? Wx1 : Wh1);
        float x = src[(size_t)kk * NG + kg0 + j];
        __nv_bfloat16 hi = __float2bfloat16_rn(x);
        int row = m * 8 + j;
        sBhi[row * RPITCH + kk] = hi;
        sBlo[row * RPITCH + kk] = __float2bfloat16_rn(x - __bfloat162float(hi));
    }
    const float b1v = b1[kg0 + c];

    const uint32_t usm  = (uint32_t)__cvta_generic_to_shared(smc);
    const uint32_t uBhi = usm + OFF_BHI;
    const uint32_t uBlo = usm + OFF_BLO;
    const uint32_t uA0  = usm + OFF_A;
    const uint32_t uA1  = uA0 + PLANE_B;
    const uint32_t uA2  = uA1 + PLANE_B;
    const uint32_t uA3  = uA2 + PLANE_B;

    const int a_row = lane & 15;
    const int a_k   = (lane >> 4) * 8;
    const int b_row = (lane & 7) + ((lane >> 4) << 3);
    const int b_k   = ((lane >> 3) & 1) * 8;
    const int k0w   = warp * 32;

    float c1 = 0.f, c2 = 0.f;

    for (int r = 0; r <= SEQ; r++) {
        int s0 = (r < SEQ) ? r : SEQ - 1;
        float gx0v = g_gx[(size_t)s0 * BATCH * NG + (size_t)b * NG + kg0 + c];

        if (r > 0 && t == 0) {
            while (*(volatile unsigned*)&g_flag < (unsigned)r) { }
            __threadfence();
        }
        __syncthreads();

        {
            const __nv_bfloat16* gp[4] = { g_h1hi[r & 1], g_h1lo[r & 1],
                                           g_h2hi[r & 1], g_h2lo[r & 1] };
            #pragma unroll
            for (int p = 0; p < 4; p++) {
                __nv_bfloat16* sAp = (__nv_bfloat16*)(smc + OFF_A + p * PLANE_B);
                #pragma unroll
                for (int i = 0; i < 4; i++) {
                    int cc = t + i * 256;
                    int row = cc >> 5, c16 = cc & 31;
                    *(uint4*)&sAp[row * RPITCH + c16 * 8] =
                        __ldcg((const uint4*)(gp[p] + row * NH + c16 * 8));
                }
            }
        }
        __syncthreads();

        float z0a[2][4], z1a[2][4];
        #pragma unroll
        for (int m = 0; m < 2; m++)
            #pragma unroll
            for (int q = 0; q < 4; q++) { z0a[m][q] = 0.f; z1a[m][q] = 0.f; }

        #pragma unroll
        for (int kc = 0; kc < 2; kc++) {
            const int k0 = k0w + kc * 16;
            uint32_t ah1h[2][4], ah1l[2][4], ah2h[2][4], ah2l[2][4];
            #pragma unroll
            for (int m = 0; m < 2; m++) {
                uint32_t ro = (uint32_t)((m * 16 + a_row) * RPITCH + k0 + a_k) * 2;
                LDM_A(ah1h[m][0], ah1h[m][1], ah1h[m][2], ah1h[m][3], uA0 + ro);
                LDM_A(ah1l[m][0], ah1l[m][1], ah1l[m][2], ah1l[m][3], uA1 + ro);
                LDM_A(ah2h[m][0], ah2h[m][1], ah2h[m][2], ah2h[m][3], uA2 + ro);
                LDM_A(ah2l[m][0], ah2l[m][1], ah2l[m][2], ah2l[m][3], uA3 + ro);
            }
            uint32_t w0h[2], wxh[2], w1h[2], w0l[2], wxl[2], w1l[2];
            {
                uint32_t ro = (uint32_t)(b_row * RPITCH + k0 + b_k) * 2;
                uint32_t r0, r1, r2, r3;
                LDM_A(r0, r1, r2, r3, uBhi + ro);
                w0h[0] = r0; w0h[1] = r1; wxh[0] = r2; wxh[1] = r3;
                LDM_A(r0, r1, r2, r3, uBlo + ro);
                w0l[0] = r0; w0l[1] = r1; wxl[0] = r2; wxl[1] = r3;
                uint32_t ro2 = (uint32_t)((16 + b_row) * RPITCH + k0 + b_k) * 2;
                LDM_A(r0, r1, r2, r3, uBhi + ro2);
                w1h[0] = r0; w1h[1] = r1;
                LDM_A(r0, r1, r2, r3, uBlo + ro2);
                w1l[0] = r0; w1l[1] = r1;
            }
            #pragma unroll
            for (int m = 0; m < 2; m++) {
                MMA_BF16(z0a[m], ah1h[m], w0h);
                MMA_BF16(z0a[m], ah1h[m], w0l);
                MMA_BF16(z0a[m], ah1l[m], w0h);
                MMA_BF16(z1a[m], ah1h[m], wxh);
                MMA_BF16(z1a[m], ah1h[m], wxl);
                MMA_BF16(z1a[m], ah1l[m], wxh);
                MMA_BF16(z1a[m], ah2h[m], w1h);
                MMA_BF16(z1a[m], ah2h[m], w1l);
                MMA_BF16(z1a[m], ah2l[m], w1h);
            }
        }

        // A planes dead from here; guard before overwriting with partials
        __syncthreads();
        {
            const int g  = lane >> 2;
            const int t4 = lane & 3;
            #pragma unroll
            for (int m = 0; m < 2; m++) {
                int rowb = m * 16 + g;
                float* p0 = sPart + (0 * 32 + rowb) * 64 + (2 * t4) * 8 + warp;
                float* p1 = sPart + (1 * 32 + rowb) * 64 + (2 * t4) * 8 + warp;
                p0[0] = z0a[m][0]; p0[8] = z0a[m][1]; p0[512] = z0a[m][2]; p0[520] = z0a[m][3];
                p1[0] = z1a[m][0]; p1[8] = z1a[m][1]; p1[512] = z1a[m][2]; p1[520] = z1a[m][3];
            }
        }
        __syncthreads();

        float z0 = gx0v, z1 = b1v;
        {
            const float* q0 = sPart + b * 64 + c * 8;
            const float* q1 = sPart + (32 + b) * 64 + c * 8;
            float4 v0 = *(const float4*)q0, v1 = *(const float4*)(q0 + 4);
            z0 += v0.x + v0.y + v0.z + v0.w + v1.x + v1.y + v1.z + v1.w;
            float4 u0 = *(const float4*)q1, u1 = *(const float4*)(q1 + 4);
            z1 += u0.x + u0.y + u0.z + u0.w + u1.x + u1.y + u1.z + u1.w;
        }

        float zi0 = __shfl_sync(0xffffffffu, z0, base + 0);
        float zf0 = __shfl_sync(0xffffffffu, z0, base + 1);
        float zo0 = __shfl_sync(0xffffffffu, z0, base + 2);
        float zg0 = __shfl_sync(0xffffffffu, z0, base + 3);
        float zi1 = __shfl_sync(0xffffffffu, z1, base + 0);
        float zf1 = __shfl_sync(0xffffffffu, z1, base + 1);
        float zo1 = __shfl_sync(0xffffffffu, z1, base + 2);
        float zg1 = __shfl_sync(0xffffffffu, z1, base + 3);

        if (owner) {
            int np = (r + 1) & 1;
            if (r < SEQ) {
                float ig = 1.f / (1.f + __expf(-zi0));
                float fg = 1.f / (1.f + __expf(-zf0));
                float og = 1.f / (1.f + __expf(-zo0));
                float gg = tanhf(zg0);
                c1 = fg * c1 + ig * gg;
                float hn = og * tanhf(c1);
                __nv_bfloat16 hb = __float2bfloat16_rn(hn);
                g_h1hi[np][b * NH + k] = hb;
                g_h1lo[np][b * NH + k] = __float2bfloat16_rn(hn - __bfloat162float(hb));
                if (r == SEQ - 1) h1_out[b * NH + k] = hn;
            }
            if (r >= 1) {
                int s1 = r - 1;
                float ig = 1.f / (1.f + __expf(-zi1));
                float fg = 1.f / (1.f + __expf(-zf1));
                float og = 1.f / (1.f + __expf(-zo1));
                float gg = tanhf(zg1);
                c2 = fg * c2 + ig * gg;
                float hn = og * tanhf(c2);
                __nv_bfloat16 hb = __float2bfloat16_rn(hn);
                __nv_bfloat16 lb = __float2bfloat16_rn(hn - __bfloat162float(hb));
                g_h2hi[np][b * NH + k] = hb;
                g_h2lo[np][b * NH + k] = lb;
                size_t m = (size_t)s1 * BATCH + b;
                g_Ahi[m * NH + k] = hb;
                g_Alo[m * NH + k] = lb;
                if (s1 == SEQ - 1) h2_out[b * NH + k] = hn;
            }
        }

        if (r < SEQ) {
            __syncthreads();
            if (t == 0) {
                __threadfence();
                unsigned old = atomicAdd(&g_cnt, 1u);
                if (old == (unsigned)r * NRC + NRC - 1u)
                    atomicExch(&g_flag, (unsigned)(r + 1));
            }
        }
    }

    // final arrival: publish round-256 g_Ahi writes -> flag = SEQ+1
    __syncthreads();
    if (t == 0) {
        __threadfence();
        unsigned old = atomicAdd(&g_cnt, 1u);
        if (old == (unsigned)SEQ * NRC + NRC - 1u)
            atomicExch(&g_flag, (unsigned)(SEQ + 1));
    }
}

// ---------------- decoder path (cp.async double-buffered, flag-gated) ----------------
__device__ __forceinline__ void decoder_path(
    char* dsm, int mi, int ni,
    const float* __restrict__ bias, float* __restrict__ out)
{
    const int t    = threadIdx.x;
    const int warp = t >> 5;
    const int lane = t & 31;
    const int m0   = mi * 128;
    const int n0   = ni * 128;
    const int wm   = warp >> 2;
    const int wn   = warp & 3;

    // wait for steps 4mi..4mi+3 of g_Ahi/g_Alo to be final
    if (t == 0) {
        unsigned tgt = 4u * (unsigned)mi + 5u;
        while (*(volatile unsigned*)&g_flag < tgt) { }
        __threadfence();
    }
    __syncthreads();

    float acc[4][4][4];
    #pragma unroll
    for (int i = 0; i < 4; i++)
        #pragma unroll
        for (int j = 0; j < 4; j++)
            #pragma unroll
            for (int q = 0; q < 4; q++) acc[i][j][q] = 0.f;

    const uint32_t usm = (uint32_t)__cvta_generic_to_shared(dsm);

    const int a_row = (lane & 15);
    const int a_k   = (lane >> 4) * 8;
    const int b_row = (lane & 7) + ((lane >> 4) << 3);
    const int b_k   = ((lane >> 3) & 1) * 8;

    int rowL[2], qL[2];
    #pragma unroll
    for (int h = 0; h < 2; h++) { int cc = t + h * 256; rowL[h] = cc >> 2; qL[h] = cc & 3; }

    auto issue = [&](int kc, int s) {
        const int k0 = kc * 32;
        uint32_t sb = usm + (uint32_t)s * DSTAGE;
        #pragma unroll
        for (int h = 0; h < 2; h++) {
            int row = rowL[h], q = qL[h];
            uint32_t so = (uint32_t)(row * 40 + q * 8) * 2;
            size_t gA = (size_t)(m0 + row) * NH + k0 + q * 8;
            size_t gB = (size_t)(n0 + row) * NH + k0 + q * 8;
            CP_ASYNC16(sb + 0 * DTILE + so, g_Ahi + gA);
            CP_ASYNC16(sb + 1 * DTILE + so, g_Alo + gA);
            CP_ASYNC16(sb + 2 * DTILE + so, g_Whi + gB);
            CP_ASYNC16(sb + 3 * DTILE + so, g_Wlo + gB);
        }
        CP_COMMIT();
    };

    issue(0, 0);

    for (int kc = 0; kc < 8; kc++) {
        if (kc < 7) issue(kc + 1, (kc + 1) & 1);
        if (kc < 7) { CP_WAIT1(); } else { CP_WAIT0(); }
        __syncthreads();

        const uint32_t sb   = usm + (uint32_t)(kc & 1) * DSTAGE;
        const uint32_t bAhi = sb + 0 * DTILE;
        const uint32_t bAlo = sb + 1 * DTILE;
        const uint32_t bBhi = sb + 2 * DTILE;
        const uint32_t bBlo = sb + 3 * DTILE;

        #pragma unroll
        for (int ks = 0; ks < 32; ks += 16) {
            uint32_t af[4][4];
            uint32_t bh[4][2], bl[4][2];

            #pragma unroll
            for (int nh = 0; nh < 2; nh++) {
                int roff = (wn * 32 + nh * 16 + b_row) * 40 + ks + b_k;
                uint32_t r0, r1, r2, r3;
                LDM_A(r0, r1, r2, r3, bBhi + roff * 2);
                bh[2*nh][0] = r0; bh[2*nh][1] = r1;
                bh[2*nh+1][0] = r2; bh[2*nh+1][1] = r3;
                LDM_A(r0, r1, r2, r3, bBlo + roff * 2);
                bl[2*nh][0] = r0; bl[2*nh][1] = r1;
                bl[2*nh+1][0] = r2; bl[2*nh+1][1] = r3;
            }
            #pragma unroll
            for (int mi2 = 0; mi2 < 4; mi2++) {
                int roff = (wm * 64 + mi2 * 16 + a_row) * 40 + ks + a_k;
                LDM_A(af[mi2][0], af[mi2][1], af[mi2][2], af[mi2][3], bAhi + roff * 2);
            }
            #pragma unroll
            for (int mi2 = 0; mi2 < 4; mi2++)
                #pragma unroll
                for (int ni2 = 0; ni2 < 4; ni2++) {
                    MMA_BF16(acc[mi2][ni2], af[mi2], bh[ni2]);
                    MMA_BF16(acc[mi2][ni2], af[mi2], bl[ni2]);
                }
            #pragma unroll
            for (int mi2 = 0; mi2 < 4; mi2++) {
                int roff = (wm * 64 + mi2 * 16 + a_row) * 40 + ks + a_k;
                LDM_A(af[mi2][0], af[mi2][1], af[mi2][2], af[mi2][3], bAlo + roff * 2);
            }
            #pragma unroll
            for (int mi2 = 0; mi2 < 4; mi2++)
                #pragma unroll
                for (int ni2 = 0; ni2 < 4; ni2++)
                    MMA_BF16(acc[mi2][ni2], af[mi2], bh[ni2]);
        }
        __syncthreads();
    }

    const int g  = lane >> 2;
    const int t4 = lane & 3;
    #pragma unroll
    for (int mi2 = 0; mi2 < 4; mi2++) {
        #pragma unroll
        for (int ni2 = 0; ni2 < 4; ni2++) {
            int col = n0 + wn * 32 + ni2 * 8 + t4 * 2;
            if (col < NVOC) {
                float b0 = bias[col], b1 = bias[col + 1];
                int row0 = m0 + wm * 64 + mi2 * 16 + g;
                float2 v0 = make_float2(acc[mi2][ni2][0] + b0, acc[mi2][ni2][1] + b1);
                float2 v1 = make_float2(acc[mi2][ni2][2] + b0, acc[mi2][ni2][3] + b1);
                *(float2*)(out + (size_t)row0 * NVOC + col) = v0;
                *(float2*)(out + (size_t)(row0 + 8) * NVOC + col) = v1;
            }
        }
    }
}

// ---------------- fused persistent kernel: recurrence CTAs + decoder CTAs ----------------
__global__ __launch_bounds__(256, 2) void fused_all(
    const float* __restrict__ Wh0,
    const float* __restrict__ Wx1,
    const float* __restrict__ Wh1,
    const float* __restrict__ b1,
    float*       __restrict__ h1_out,
    float*       __restrict__ h2_out,
    const float* __restrict__ dec_b,
    float*       __restrict__ out)
{
    extern __shared__ char smc[];
    if (blockIdx.x < NRC) {
        recurrence_path(smc, Wh0, Wx1, Wh1, b1, h1_out, h2_out);
    } else {
        int idx = blockIdx.x - NRC;
        int mi = idx / 79;
        int ni = idx % 79;
        decoder_path(smc, mi, ni, dec_b, out);
    }
}

// ---------------- bf16 split of decoder weights (scalar — proven) ----------------
__global__ __launch_bounds__(256) void conv_W(const float* __restrict__ W) {
    int i = blockIdx.x * blockDim.x + threadIdx.x;
    if (i < NVPAD * NH) {
        int v = i >> 8;
        float x = (v < NVOC) ? W[(size_t)v * NH + (i & 255)] : 0.f;
        __nv_bfloat16 hi = __float2bfloat16_rn(x);
        g_Whi[i] = hi;
        g_Wlo[i] = __float2bfloat16_rn(x - __bfloat162float(hi));
    }
}

// ---------------- launch ----------------
extern "C" void kernel_launch(void* const* d_in, const int* in_sizes, int n_in,
                              void* d_out, int out_size) {
    const int*   tokens  = (const int*)  d_in[0];
    const float* embed_W = (const float*)d_in[1];
    const float* Wx0     = (const float*)d_in[2];
    const float* Wh0     = (const float*)d_in[3];
    const float* b0      = (const float*)d_in[4];
    const float* Wx1     = (const float*)d_in[5];
    const float* Wh1     = (const float*)d_in[6];
    const float* b1      = (const float*)d_in[7];
    const float* dec_W   = (const float*)d_in[8];
    const float* dec_b   = (const float*)d_in[9];
    (void)in_sizes; (void)n_in;

    float* out    = (float*)d_out;
    float* h1_out = out + (size_t)out_size - 2 * BATCH * NH;
    float* h2_out = out + (size_t)out_size - 1 * BATCH * NH;

    static bool attr_done = false;
    if (!attr_done) {
        cudaFuncSetAttribute(fused_all, cudaFuncAttributeMaxDynamicSharedMemorySize, RS_BYTES);
        attr_done = true;
    }

    conv_W<<<(NVPAD * NH + 255) / 256, 256>>>(dec_W);
    init_state<<<16, 256>>>();
    gemm_gx<<<dim3(8, 64), 256>>>(embed_W, tokens, Wx0, b0);
    fused_all<<<NRC + NDT, 256, RS_BYTES>>>(Wh0, Wx1, Wh1, b1, h1_out, h2_out, dec_b, out);
}